// round 4
// baseline (speedup 1.0000x reference)
#include <cuda_runtime.h>
#include <cstdint>

#define ROWS 131072
#define COLS 256
#define NM   128
#define WPB  8                    // warps per block (one row per warp)
#define THREADS (WPB * 32)

// Output = concat(masked_data, masked_indices, unmasked_data, unmasked_indices),
// each [ROWS, 128] row-major f32.
__global__ void __launch_bounds__(THREADS)
masker_kernel(const float* __restrict__ x,
              const int*   __restrict__ perm,
              float* __restrict__ out) {
    const int warp_id = threadIdx.x >> 5;
    const int lane    = threadIdx.x & 31;
    const int row     = blockIdx.x * WPB + warp_id;

    __shared__ int   member[WPB][COLS];     // membership; reused as x stage
    __shared__ float stage[WPB][3 * NM];    // [mi | ud | ui]

    int* mem = member[warp_id];

    // ---- front-batch ALL global loads (MLP=3, streaming hint) ----
    const int4*   prow  = reinterpret_cast<const int4*>(perm + (size_t)row * COLS);
    const float4* xrow4 = reinterpret_cast<const float4*>(x + (size_t)row * COLS);
    int4   mh = __ldcs(prow + lane);        // masked half of permutation
    float4 xa = __ldcs(xrow4 + lane);       // x[4*lane .. 4*lane+3]
    float4 xb = __ldcs(xrow4 + lane + 32);  // x[128+4*lane ..]

    // ---- membership table ----
#pragma unroll
    for (int k = 0; k < 8; k++) mem[lane + 32 * k] = 0;
    __syncwarp();
    mem[mh.x] = 1;
    mem[mh.y] = 1;
    mem[mh.z] = 1;
    mem[mh.w] = 1;
    __syncwarp();

    unsigned mask[8];
#pragma unroll
    for (int w = 0; w < 8; w++)
        mask[w] = __ballot_sync(0xffffffffu, mem[32 * w + lane] != 0);

    int base[8];
    int acc = 0;
#pragma unroll
    for (int w = 0; w < 8; w++) { base[w] = acc; acc += __popc(mask[w]); }

    // ---- stage x row in shared (reuse membership storage) ----
    float* xbuf = reinterpret_cast<float*>(mem);
    reinterpret_cast<float4*>(xbuf)[lane]      = xa;
    reinterpret_cast<float4*>(xbuf)[lane + 32] = xb;

    float* smi = stage[warp_id];
    float* sud = stage[warp_id] + NM;
    float* sui = stage[warp_id] + 2 * NM;
    __syncwarp();

    // ---- rank + scatter into shared stage ----
#pragma unroll
    for (int w = 0; w < 8; w++) {
        const int c = 32 * w + lane;
        const unsigned below = mask[w] & ((1u << lane) - 1u);
        const int mrank = base[w] + __popc(below);      // # masked < c
        if ((mask[w] >> lane) & 1u) {
            smi[mrank] = (float)c;
        } else {
            const int urank = c - mrank;                // # unmasked < c
            sud[urank] = xbuf[c];
            sui[urank] = (float)c;
        }
    }
    __syncwarp();

    // ---- coalesced streaming write-out ----
    const size_t seg = (size_t)ROWS * NM;
    float4* o_md = reinterpret_cast<float4*>(out + (size_t)row * NM);
    float4* o_mi = reinterpret_cast<float4*>(out + seg     + (size_t)row * NM);
    float4* o_ud = reinterpret_cast<float4*>(out + 2 * seg + (size_t)row * NM);
    float4* o_ui = reinterpret_cast<float4*>(out + 3 * seg + (size_t)row * NM);

    __stcs(o_md + lane, make_float4(0.f, 0.f, 0.f, 0.f));
    __stcs(o_mi + lane, reinterpret_cast<float4*>(smi)[lane]);
    __stcs(o_ud + lane, reinterpret_cast<float4*>(sud)[lane]);
    __stcs(o_ui + lane, reinterpret_cast<float4*>(sui)[lane]);
}

extern "C" void kernel_launch(void* const* d_in, const int* in_sizes, int n_in,
                              void* d_out, int out_size) {
    const float* x    = (const float*)d_in[0];
    const int*   perm = (const int*)d_in[1];
    float* out = (float*)d_out;

    masker_kernel<<<ROWS / WPB, THREADS>>>(x, perm, out);
}

// round 6
// speedup vs baseline: 1.3338x; 1.3338x over previous
#include <cuda_runtime.h>
#include <cstdint>

#define ROWS 131072
#define COLS 256
#define NM   128
#define WPB  8                    // warps per block (one row per warp)
#define THREADS (WPB * 32)

// Output = concat(masked_data, masked_indices, unmasked_data, unmasked_indices),
// each [ROWS, 128] row-major f32.
__global__ void __launch_bounds__(THREADS)
masker_kernel(const float* __restrict__ x,
              const int*   __restrict__ perm,
              float* __restrict__ out) {
    const int warp_id = threadIdx.x >> 5;
    const int lane    = threadIdx.x & 31;
    const int row     = blockIdx.x * WPB + warp_id;

    __shared__ int   member[WPB][COLS];     // membership table
    __shared__ float stage[WPB][3 * NM];    // [mi | ud | ui]

    int* mem = member[warp_id];

    // ---- global loads, front-batched (plain caching; .cs regressed) ----
    const int4*   prow  = reinterpret_cast<const int4*>(perm + (size_t)row * COLS);
    const float4* xrow4 = reinterpret_cast<const float4*>(x + (size_t)row * COLS);
    int4   mh = prow[lane];         // masked half of permutation
    float4 xa = xrow4[lane];        // x[4*lane .. 4*lane+3]
    float4 xb = xrow4[lane + 32];   // x[128+4*lane ..]

    // ---- membership table ----
#pragma unroll
    for (int k = 0; k < 8; k++) mem[lane + 32 * k] = 0;
    __syncwarp();
    mem[mh.x] = 1;
    mem[mh.y] = 1;
    mem[mh.z] = 1;
    mem[mh.w] = 1;
    __syncwarp();

    // 256-bit membership bitmap as 8 ballot words (uniform across warp)
    unsigned mask[8];
#pragma unroll
    for (int w = 0; w < 8; w++)
        mask[w] = __ballot_sync(0xffffffffu, mem[32 * w + lane] != 0);

    int base[8];                    // masked-count prefix
    int acc = 0;
#pragma unroll
    for (int w = 0; w < 8; w++) { base[w] = acc; acc += __popc(mask[w]); }

    float* smi = stage[warp_id];
    float* sud = stage[warp_id] + NM;
    float* sui = stage[warp_id] + 2 * NM;

    // Compile-time SEL trees: word index for this lane's column group.
    // Half 0: cols 4*lane+j  -> word w0 = lane>>3 (0..3)
    // Half 1: cols 128+4*lane+j -> word w1 = 4 + (lane>>3)
    const bool hi = (lane & 16) != 0;
    const bool md = (lane & 8)  != 0;
    const unsigned mw0 = hi ? (md ? mask[3] : mask[2]) : (md ? mask[1] : mask[0]);
    const int      b0  = hi ? (md ? base[3] : base[2]) : (md ? base[1] : base[0]);
    const unsigned mw1 = hi ? (md ? mask[7] : mask[6]) : (md ? mask[5] : mask[4]);
    const int      b1  = hi ? (md ? base[7] : base[6]) : (md ? base[5] : base[4]);

    // ---- rank + scatter into stage, x straight from registers ----
    const float xv0[4] = {xa.x, xa.y, xa.z, xa.w};
    const float xv1[4] = {xb.x, xb.y, xb.z, xb.w};

#pragma unroll
    for (int j = 0; j < 4; j++) {
        const int c   = 4 * lane + j;
        const int bit = c & 31;
        const int mrank = b0 + __popc(mw0 & ((1u << bit) - 1u));
        if ((mw0 >> bit) & 1u) {
            smi[mrank] = (float)c;
        } else {
            const int urank = c - mrank;
            sud[urank] = xv0[j];
            sui[urank] = (float)c;
        }
    }
#pragma unroll
    for (int j = 0; j < 4; j++) {
        const int c   = 128 + 4 * lane + j;
        const int bit = c & 31;
        const int mrank = b1 + __popc(mw1 & ((1u << bit) - 1u));
        if ((mw1 >> bit) & 1u) {
            smi[mrank] = (float)c;
        } else {
            const int urank = c - mrank;
            sud[urank] = xv1[j];
            sui[urank] = (float)c;
        }
    }
    __syncwarp();

    // ---- coalesced write-out ----
    const size_t seg = (size_t)ROWS * NM;
    float4* o_md = reinterpret_cast<float4*>(out + (size_t)row * NM);
    float4* o_mi = reinterpret_cast<float4*>(out + seg     + (size_t)row * NM);
    float4* o_ud = reinterpret_cast<float4*>(out + 2 * seg + (size_t)row * NM);
    float4* o_ui = reinterpret_cast<float4*>(out + 3 * seg + (size_t)row * NM);

    o_md[lane] = make_float4(0.f, 0.f, 0.f, 0.f);
    o_mi[lane] = reinterpret_cast<float4*>(smi)[lane];
    o_ud[lane] = reinterpret_cast<float4*>(sud)[lane];
    o_ui[lane] = reinterpret_cast<float4*>(sui)[lane];
}

extern "C" void kernel_launch(void* const* d_in, const int* in_sizes, int n_in,
                              void* d_out, int out_size) {
    const float* x    = (const float*)d_in[0];
    const int*   perm = (const int*)d_in[1];
    float* out = (float*)d_out;

    masker_kernel<<<ROWS / WPB, THREADS>>>(x, perm, out);
}